// round 13
// baseline (speedup 1.0000x reference)
#include <cuda_runtime.h>
#include <cuda_fp16.h>
#include <cstdint>

#define BATCH  8
#define LSEQ   1024
#define DMODEL 512
#define NHEAD  8
#define DKH    64
#define DVH    512
#define MTOT   (BATCH*LSEQ)

// ---------------- scratch (static device globals, zero-initialized) ---------
__device__ __align__(256) __half g_ench[MTOT*DMODEL];
__device__ __align__(256) __half g_Wqh [DMODEL*DMODEL];
__device__ __align__(256) __half g_Wkh [DMODEL*DMODEL];
__device__ __align__(256) __half g_Wvh [NHEAD*DVH*DMODEL];
__device__ __align__(256) __half g_Wgh [NHEAD*DVH*DMODEL];
__device__ __align__(256) __half g_Wfch[DMODEL*DVH];
__device__ __align__(256) __half g_Q [NHEAD*MTOT*DKH];       // [h][m][dk]
__device__ __align__(256) __half g_K [NHEAD*MTOT*DKH];       // [h][m][dk]
__device__ __align__(256) __half g_Vt[NHEAD*BATCH*DVH*LSEQ]; // [h][b][dv][l]
__device__ __align__(256) __half g_S [67108864];             // [hb][q][k] fp16
__device__ __align__(256) __half g_P [67108864];             // softmax(S) fp16
__device__ __align__(256) __half g_O [NHEAD*MTOT*DVH];       // [h][m][dv]
__device__ __align__(256) __half g_G [NHEAD*MTOT*DVH];
__device__ __align__(256) __half g_Y [MTOT*DVH];
__device__ int   g_len[BATCH];

// ---------------- helpers ----------------------------------------------------
__device__ __forceinline__ uint32_t smem_u32(const void* p) {
    uint32_t a;
    asm("{ .reg .u64 t; cvta.to.shared.u64 t, %1; cvt.u32.u64 %0, t; }"
        : "=r"(a) : "l"(p));
    return a;
}
__device__ __forceinline__ void cp16(uint32_t s, const void* g) {
    asm volatile("cp.async.cg.shared.global [%0], [%1], 16;" :: "r"(s), "l"(g));
}
__device__ __forceinline__ void ldsm4(uint32_t& r0, uint32_t& r1,
                                      uint32_t& r2, uint32_t& r3, uint32_t a) {
    asm volatile("ldmatrix.sync.aligned.m8n8.x4.shared.b16 {%0,%1,%2,%3}, [%4];"
                 : "=r"(r0), "=r"(r1), "=r"(r2), "=r"(r3) : "r"(a));
}
__device__ __forceinline__ void mma_f16(float& c0, float& c1, float& c2, float& c3,
                                        uint32_t a0, uint32_t a1, uint32_t a2, uint32_t a3,
                                        uint32_t b0, uint32_t b1) {
    asm volatile("mma.sync.aligned.m16n8k16.row.col.f32.f16.f16.f32 "
                 "{%0,%1,%2,%3}, {%4,%5,%6,%7}, {%8,%9}, {%0,%1,%2,%3};"
                 : "+f"(c0), "+f"(c1), "+f"(c2), "+f"(c3)
                 : "r"(a0), "r"(a1), "r"(a2), "r"(a3), "r"(b0), "r"(b1));
}

// ---------------- fp32 -> fp16 conversion of enc + weights -------------------
#define N_ENC (MTOT*DMODEL)
#define N_WQ  (DMODEL*DMODEL)
#define N_WV  (NHEAD*DVH*DMODEL)
__global__ void convert_inputs(const float* __restrict__ enc,
                               const float* __restrict__ wq,
                               const float* __restrict__ wk,
                               const float* __restrict__ wv,
                               const float* __restrict__ wg,
                               const float* __restrict__ wfc) {
    const long long i4 = ((long long)blockIdx.x * 256 + threadIdx.x) * 4;
    const float* src; __half* dst; long long off;
    if      (i4 < N_ENC)                   { src = enc; dst = g_ench; off = i4; }
    else if (i4 < N_ENC + N_WQ)            { src = wq;  dst = g_Wqh;  off = i4 - N_ENC; }
    else if (i4 < N_ENC + 2*N_WQ)          { src = wk;  dst = g_Wkh;  off = i4 - N_ENC - N_WQ; }
    else if (i4 < N_ENC + 2*N_WQ + N_WV)   { src = wv;  dst = g_Wvh;  off = i4 - N_ENC - 2*N_WQ; }
    else if (i4 < N_ENC + 2*N_WQ + 2*N_WV) { src = wg;  dst = g_Wgh;  off = i4 - N_ENC - 2*N_WQ - N_WV; }
    else if (i4 < N_ENC + 3*N_WQ + 2*N_WV) { src = wfc; dst = g_Wfch; off = i4 - N_ENC - 2*N_WQ - 2*N_WV; }
    else return;
    const float4 v = *reinterpret_cast<const float4*>(src + off);
    __half2* d2 = reinterpret_cast<__half2*>(dst + off);
    d2[0] = __floats2half2_rn(v.x, v.y);
    d2[1] = __floats2half2_rn(v.z, v.w);
}

// ---------------- mask prep --------------------------------------------------
__global__ void prep_mask(const unsigned char* __restrict__ mask8) {
    __shared__ int s_violate;
    __shared__ int s_len[BATCH];
    const int t = threadIdx.x;
    if (t == 0) s_violate = 0;
    if (t < BATCH) s_len[t] = LSEQ;
    __syncthreads();
    for (int i = t; i < BATCH*LSEQ - 1; i += blockDim.x) {
        if ((i & (LSEQ-1)) != LSEQ-1) {
            if (mask8[i] != 0 && mask8[i+1] == 0) atomicOr(&s_violate, 1);
        }
    }
    __syncthreads();
    const bool is4 = (s_violate != 0);
    if (!is4) {
        for (int i = t; i < BATCH*LSEQ; i += blockDim.x)
            if (mask8[i] != 0) atomicMin(&s_len[i >> 10], i & (LSEQ-1));
    } else {
        const unsigned int* m32 = reinterpret_cast<const unsigned int*>(mask8);
        for (int i = t; i < BATCH*LSEQ; i += blockDim.x)
            if (m32[i] != 0) atomicMin(&s_len[i >> 10], i & (LSEQ-1));
    }
    __syncthreads();
    if (t < BATCH) g_len[t] = s_len[t];
}

// ---------------- fp16 mma GEMM: C = A @ B^T ---------------------------------
// CTA tile 128x64, BK=64 halfs, 256 threads = 8 warps (4m x 2n grid),
// warp tile 32x32 (acc 32 floats/thread -> ~80 regs -> 3 CTAs/SM, 24 warps),
// 2-stage cp.async pipeline, ldmatrix.x4 fragment loads.
// MODE: 7 fp16 plain batched (S, O); 3 fp16 +bias[batch*sBias+n] (gate);
//       4 fp32 final (+bias+resid, pad0); 5 fused QKV (bx<8 Q, <16 K -> fp16
//       [h][m][dk]; else V -> transposed fp16 Vt[h][b][dv][l] via smem staging)
// SKIP: 1 row-tile skip; 2 S row+col skip; 3 PV row skip + K clamp;
//       4 final zero-fill padded rows.
#define ASTRH   72
#define ABYTES  (128*ASTRH*2)       // 18432 (A: 128 rows)
#define BBYTES  (64*ASTRH*2)        // 9216  (B: 64 rows)
#define STAGEB  (ABYTES + BBYTES)   // 27648
#define SMEM_SZ (2*STAGEB)          // 55296
#define SREG    136

template<int MODE, int SKIP>
__global__ void __launch_bounds__(256, 3)
gemm_mma(const __half* __restrict__ A, long long sA,
         const __half* __restrict__ Bm, long long sB,
         int M, int N, int K,
         void* __restrict__ C, long long sC,
         const float* __restrict__ bias, int sBias,
         const float* __restrict__ resid,
         const __half* B2, const float* bias2, void* C2,
         const __half* B3, const float* bias3, void* C3)
{
    extern __shared__ char dsm[];
    const int tid  = threadIdx.x;
    const int w    = tid >> 5;
    const int lane = tid & 31;
    const int wm   = w & 3;         // 4 m-positions of 32 rows
    const int wn   = w >> 2;        // 2 n-positions of 32 cols
    const int batch = blockIdx.z;
    const int bm = blockIdx.y * 128;

    const __half* Bsrc = Bm;
    const float* biasp = bias;
    void* Cp = C;
    int bn = blockIdx.x * 64;
    int smode = MODE;
    if (MODE == 5) {
        const int bx = blockIdx.x;
        if (bx < 8)       { smode = 0; bn = bx * 64; }
        else if (bx < 16) { smode = 0; bn = (bx-8) * 64; Bsrc = B2; biasp = bias2; Cp = C2; }
        else              { smode = 6; bn = (bx-16) * 64; Bsrc = B3; biasp = bias3; Cp = C3; }
    }

    int Keff = K;
    if (SKIP == 1) {
        if ((bm & (LSEQ-1)) >= g_len[bm >> 10]) return;
    } else if (SKIP == 2) {
        const int L = g_len[batch & (BATCH-1)];
        if (bm >= L || bn >= L) return;
    } else if (SKIP == 3) {
        const int L = g_len[batch & (BATCH-1)];
        if (bm >= L) return;
        Keff = (L + 63) & ~63;
    } else if (SKIP == 4) {
        if ((bm & (LSEQ-1)) >= g_len[bm >> 10]) {
            float* Cf = (float*)Cp;
            const float4 z = {0.f, 0.f, 0.f, 0.f};
            for (int i = 0; i < 8; i++) {
                const int idx = tid + i*256;
                const int r = idx >> 4, c4 = idx & 15;
                *reinterpret_cast<float4*>(&Cf[(long long)(bm + r)*N + bn + c4*4]) = z;
            }
            return;
        }
    }

    const __half* Ab = A    + (long long)batch * sA;
    const __half* Bb = Bsrc + (long long)batch * sB;
    const uint32_t smem0 = smem_u32(dsm);
    const int KC = Keff >> 6;

    auto load_stage = [&](int kc) {
        const int st = kc & 1;
        const uint32_t sa = smem0 + st * STAGEB;
        const uint32_t sb = sa + ABYTES;
        const int k0 = kc << 6;
        #pragma unroll
        for (int i = 0; i < 4; i++) {              // A: 128 rows x 8 chunks
            const int idx = tid + i * 256;
            const int row = idx >> 3, chk = idx & 7;
            cp16(sa + row*(ASTRH*2) + chk*16,
                 Ab + (long long)(bm + row) * K + k0 + chk*8);
        }
        #pragma unroll
        for (int i = 0; i < 2; i++) {              // B: 64 rows x 8 chunks
            const int idx = tid + i * 256;
            const int row = idx >> 3, chk = idx & 7;
            cp16(sb + row*(ASTRH*2) + chk*16,
                 Bb + (long long)(bn + row) * K + k0 + chk*8);
        }
        asm volatile("cp.async.commit_group;" ::: "memory");
    };

    float acc[2][4][4];
    #pragma unroll
    for (int i = 0; i < 2; i++)
        #pragma unroll
        for (int j = 0; j < 4; j++)
            #pragma unroll
            for (int q = 0; q < 4; q++) acc[i][j][q] = 0.f;

    load_stage(0);

    const int lrow_a  = lane & 15;
    const int lkoff_a = (lane >> 4) * 8;
    const int lrow_b  = (lane & 7) + ((lane >> 4) << 3);
    const int lkoff_b = (lane & 8) ? 8 : 0;

    for (int kc = 0; kc < KC; kc++) {
        asm volatile("cp.async.wait_group 0;" ::: "memory");
        __syncthreads();
        if (kc + 1 < KC) load_stage(kc + 1);   // next buffer; overlaps compute

        const int st = kc & 1;
        const uint32_t Abase = smem0 + st * STAGEB;
        const uint32_t Bbase = Abase + ABYTES;

        #pragma unroll
        for (int ks = 0; ks < 4; ks++) {
            uint32_t af[2][4];
            #pragma unroll
            for (int mt = 0; mt < 2; mt++) {
                const uint32_t addr = Abase +
                    ((wm*32 + mt*16 + lrow_a)*ASTRH + ks*16 + lkoff_a) * 2;
                ldsm4(af[mt][0], af[mt][1], af[mt][2], af[mt][3], addr);
            }
            uint32_t bf[4][2];
            #pragma unroll
            for (int np = 0; np < 2; np++) {
                const uint32_t addr = Bbase +
                    ((wn*32 + np*16 + lrow_b)*ASTRH + ks*16 + lkoff_b) * 2;
                ldsm4(bf[np*2][0], bf[np*2][1], bf[np*2+1][0], bf[np*2+1][1], addr);
            }
            #pragma unroll
            for (int mt = 0; mt < 2; mt++)
                #pragma unroll
                for (int nt = 0; nt < 4; nt++)
                    mma_f16(acc[mt][nt][0], acc[mt][nt][1], acc[mt][nt][2], acc[mt][nt][3],
                            af[mt][0], af[mt][1], af[mt][2], af[mt][3],
                            bf[nt][0], bf[nt][1]);
        }
    }

    if (MODE == 5 && smode == 6) {   // V transposed store via smem staging
        __syncthreads();
        __half* stg = reinterpret_cast<__half*>(dsm);   // [64 dv][SREG l]
        #pragma unroll
        for (int mt = 0; mt < 2; mt++) {
            #pragma unroll
            for (int half_ = 0; half_ < 2; half_++) {
                const int ml = wm*32 + mt*16 + (lane >> 2) + half_*8;   // l-local
                #pragma unroll
                for (int nt = 0; nt < 4; nt++) {
                    const int nl = wn*32 + nt*8 + (lane & 3)*2;         // dv-local
                    const float2 bv = *reinterpret_cast<const float2*>(&biasp[bn + nl]);
                    stg[nl*SREG + ml]     = __float2half_rn(acc[mt][nt][half_*2 + 0] + bv.x);
                    stg[(nl+1)*SREG + ml] = __float2half_rn(acc[mt][nt][half_*2 + 1] + bv.y);
                }
            }
        }
        __syncthreads();
        const int h = bn >> 9, dv0 = bn & 511;
        const int b = bm >> 10, l0 = bm & (LSEQ-1);
        __half* Vt = (__half*)Cp + (((long long)h*BATCH + b)*DVH + dv0)*LSEQ + l0;
        #pragma unroll
        for (int i = 0; i < 4; i++) {               // 64 dv x 16 l-chunks of 8
            const int u = tid + i*256;
            const int dv = u >> 4, lc = u & 15;
            const uint4 o = *reinterpret_cast<const uint4*>(&stg[dv*SREG + lc*8]);
            *reinterpret_cast<uint4*>(&Vt[(long long)dv*LSEQ + lc*8]) = o;
        }
        return;
    }

    #pragma unroll
    for (int mt = 0; mt < 2; mt++) {
        const int r0 = bm + wm*32 + mt*16 + (lane >> 2);
        #pragma unroll
        for (int half_ = 0; half_ < 2; half_++) {
            const int m = r0 + half_*8;
            const int b_idx = m >> 10, l_idx = m & (LSEQ-1);
            #pragma unroll
            for (int nt = 0; nt < 4; nt++) {
                const int n = bn + wn*32 + nt*8 + (lane & 3)*2;
                const float v0 = acc[mt][nt][half_*2 + 0];
                const float v1 = acc[mt][nt][half_*2 + 1];
                if (MODE == 5) {      // QK projection: fp16 [h][m][dk] + bias
                    const float2 bv = *reinterpret_cast<const float2*>(&biasp[n]);
                    const int h = n >> 6, d = n & 63;
                    __half* Ch = (__half*)Cp;
                    *reinterpret_cast<__half2*>(&Ch[((long long)h*MTOT + m)*DKH + d]) =
                        __floats2half2_rn(v0 + bv.x, v1 + bv.y);
                } else if (MODE == 7) {   // fp16 plain batched (S, O)
                    __half* Ch = (__half*)Cp;
                    *reinterpret_cast<__half2*>(
                        &Ch[(long long)batch*sC + (long long)m*N + n]) =
                        __floats2half2_rn(v0, v1);
                } else if (MODE == 3) {   // fp16 + per-batch bias (G)
                    const float2 bv = *reinterpret_cast<const float2*>(
                        &biasp[(long long)batch*sBias + n]);
                    __half* Ch = (__half*)Cp;
                    *reinterpret_cast<__half2*>(
                        &Ch[(long long)batch*sC + (long long)m*N + n]) =
                        __floats2half2_rn(v0 + bv.x, v1 + bv.y);
                } else {                  // MODE 4: fp32 final
                    float* Cf = (float*)Cp;
                    float2 o;
                    if (l_idx >= g_len[b_idx]) { o.x = 0.f; o.y = 0.f; }
                    else {
                        const float2 bv = *reinterpret_cast<const float2*>(&biasp[n]);
                        const float2 rv = *reinterpret_cast<const float2*>(
                            &resid[(long long)m*N + n]);
                        o.x = v0 + bv.x + rv.x;
                        o.y = v1 + bv.y + rv.y;
                    }
                    *reinterpret_cast<float2*>(&Cf[(long long)m*N + n]) = o;
                }
            }
        }
    }
}

// ---------------- masked row softmax: fp16 in (S), fp16 out (P) --------------
__global__ void softmax_rows(const __half* __restrict__ S, __half* __restrict__ P) {
    const int hb  = blockIdx.y;
    const int len = g_len[hb & (BATCH-1)];
    const int q   = blockIdx.x;
    if (q >= len) return;
    const uint2* row = reinterpret_cast<const uint2*>(
        S + ((long long)hb * LSEQ + q) * LSEQ);
    __half2* prow = reinterpret_cast<__half2*>(
        P + ((long long)hb * LSEQ + q) * LSEQ);

    const int t = threadIdx.x;
    const uint2 u = row[t];
    const float2 va = __half22float2(*reinterpret_cast<const __half2*>(&u.x));
    const float2 vb = __half22float2(*reinterpret_cast<const __half2*>(&u.y));
    const int j0 = t * 4;
    const float NEG = -1e30f;
    float x0 = (j0+0 < len) ? va.x : NEG;
    float x1 = (j0+1 < len) ? va.y : NEG;
    float x2 = (j0+2 < len) ? vb.x : NEG;
    float x3 = (j0+3 < len) ? vb.y : NEG;

    __shared__ float rmax[8], rsum[8];
    float mx = fmaxf(fmaxf(x0, x1), fmaxf(x2, x3));
    #pragma unroll
    for (int o = 16; o; o >>= 1) mx = fmaxf(mx, __shfl_xor_sync(~0u, mx, o));
    if ((t & 31) == 0) rmax[t >> 5] = mx;
    __syncthreads();
    mx = rmax[0];
    #pragma unroll
    for (int i = 1; i < 8; i++) mx = fmaxf(mx, rmax[i]);
    mx *= 0.125f;

    const float e0 = __expf(x0*0.125f - mx);
    const float e1 = __expf(x1*0.125f - mx);
    const float e2 = __expf(x2*0.125f - mx);
    const float e3 = __expf(x3*0.125f - mx);
    float s = e0 + e1 + e2 + e3;
    #pragma unroll
    for (int o = 16; o; o >>= 1) s += __shfl_xor_sync(~0u, s, o);
    if ((t & 31) == 0) rsum[t >> 5] = s;
    __syncthreads();
    s = rsum[0];
    #pragma unroll
    for (int i = 1; i < 8; i++) s += rsum[i];
    const float inv = 1.f / s;

    prow[t*2]   = __floats2half2_rn(e0*inv, e1*inv);
    prow[t*2+1] = __floats2half2_rn(e2*inv, e3*inv);
}

// ---------------- head-gate softmax + weighted combine (fp16 in/out) ---------
__global__ void gate_combine(const __half* __restrict__ G,
                             const __half* __restrict__ O,
                             __half* __restrict__ Y) {
    const int HS4 = MTOT*DVH/4;
    const int i = blockIdx.x * blockDim.x + threadIdx.x;
    if (i >= HS4) return;
    const int m = i >> 7;
    if ((m & (LSEQ-1)) >= g_len[m >> 10]) return;

    const uint2* G4 = reinterpret_cast<const uint2*>(G);
    const uint2* O4 = reinterpret_cast<const uint2*>(O);
    float g[NHEAD][4];
    float mx0 = -1e30f, mx1 = -1e30f, mx2 = -1e30f, mx3 = -1e30f;
    #pragma unroll
    for (int h = 0; h < NHEAD; h++) {
        const uint2 u = G4[(long long)h*HS4 + i];
        const float2 a = __half22float2(*reinterpret_cast<const __half2*>(&u.x));
        const float2 b = __half22float2(*reinterpret_cast<const __half2*>(&u.y));
        g[h][0] = a.x; g[h][1] = a.y; g[h][2] = b.x; g[h][3] = b.y;
        mx0 = fmaxf(mx0, a.x); mx1 = fmaxf(mx1, a.y);
        mx2 = fmaxf(mx2, b.x); mx3 = fmaxf(mx3, b.y);
    }
    float acc0=0, acc1=0, acc2=0, acc3=0, s0=0, s1=0, s2=0, s3=0;
    #pragma unroll
    for (int h = 0; h < NHEAD; h++) {
        const uint2 u = O4[(long long)h*HS4 + i];
        const float2 a = __half22float2(*reinterpret_cast<const __half2*>(&u.x));
        const float2 b = __half22float2(*reinterpret_cast<const __half2*>(&u.y));
        const float e0 = __expf(g[h][0] - mx0), e1 = __expf(g[h][1] - mx1);
        const float e2 = __expf(g[h][2] - mx2), e3 = __expf(g[h][3] - mx3);
        s0 += e0; s1 += e1; s2 += e2; s3 += e3;
        acc0 += e0*a.x; acc1 += e1*a.y; acc2 += e2*b.x; acc3 += e3*b.y;
    }
    uint2 o;
    *reinterpret_cast<__half2*>(&o.x) = __floats2half2_rn(acc0/s0, acc1/s1);
    *reinterpret_cast<__half2*>(&o.y) = __floats2half2_rn(acc2/s2, acc3/s3);
    reinterpret_cast<uint2*>(Y)[i] = o;
}

// ---------------- launch ------------------------------------------------------
extern "C" void kernel_launch(void* const* d_in, const int* in_sizes, int n_in,
                              void* d_out, int out_size) {
    const float*         enc  = (const float*)d_in[0];
    const unsigned char* npm  = (const unsigned char*)d_in[1];
    const float* w_q  = (const float*)d_in[3];
    const float* b_q  = (const float*)d_in[4];
    const float* w_k  = (const float*)d_in[5];
    const float* b_k  = (const float*)d_in[6];
    const float* w_v  = (const float*)d_in[7];
    const float* b_v  = (const float*)d_in[8];
    const float* w_g  = (const float*)d_in[9];
    const float* b_g  = (const float*)d_in[10];
    const float* w_fc = (const float*)d_in[11];
    const float* b_fc = (const float*)d_in[12];
    float* out = (float*)d_out;

    __half *pEnc,*pWq,*pWk,*pWv,*pWg,*pWfc,*pQ,*pK,*pVt,*pS,*pP,*pO,*pG,*pY;
    cudaGetSymbolAddress((void**)&pEnc, g_ench);
    cudaGetSymbolAddress((void**)&pWq,  g_Wqh);
    cudaGetSymbolAddress((void**)&pWk,  g_Wkh);
    cudaGetSymbolAddress((void**)&pWv,  g_Wvh);
    cudaGetSymbolAddress((void**)&pWg,  g_Wgh);
    cudaGetSymbolAddress((void**)&pWfc, g_Wfch);
    cudaGetSymbolAddress((void**)&pQ,   g_Q);
    cudaGetSymbolAddress((void**)&pK,   g_K);
    cudaGetSymbolAddress((void**)&pVt,  g_Vt);
    cudaGetSymbolAddress((void**)&pS,   g_S);
    cudaGetSymbolAddress((void**)&pP,   g_P);
    cudaGetSymbolAddress((void**)&pO,   g_O);
    cudaGetSymbolAddress((void**)&pG,   g_G);
    cudaGetSymbolAddress((void**)&pY,   g_Y);

    cudaFuncSetAttribute(gemm_mma<5,1>, cudaFuncAttributeMaxDynamicSharedMemorySize, SMEM_SZ);
    cudaFuncSetAttribute(gemm_mma<7,2>, cudaFuncAttributeMaxDynamicSharedMemorySize, SMEM_SZ);
    cudaFuncSetAttribute(gemm_mma<7,3>, cudaFuncAttributeMaxDynamicSharedMemorySize, SMEM_SZ);
    cudaFuncSetAttribute(gemm_mma<3,1>, cudaFuncAttributeMaxDynamicSharedMemorySize, SMEM_SZ);
    cudaFuncSetAttribute(gemm_mma<4,4>, cudaFuncAttributeMaxDynamicSharedMemorySize, SMEM_SZ);

    const int M = MTOT;
    dim3 blk(256);

    convert_inputs<<<(N_ENC + 3*N_WQ + 2*N_WV) / 1024, 256>>>(enc, w_q, w_k, w_v, w_g, w_fc);
    prep_mask<<<1, 256>>>(npm);

    // Fused Q/K/V projections: 80 column segments of 64 (8 Q, 8 K, 64 V)
    gemm_mma<5,1><<<dim3(80, M/128, 1), blk, SMEM_SZ>>>(
        pEnc,0, pWq,0, M, NHEAD*DKH, DMODEL, pQ,0, b_q,0, nullptr,
        pWk, b_k, pK, pWv, b_v, pVt);
    // S = Q @ K^T per (h,b), fp16 out, masked tiles skipped
    gemm_mma<7,2><<<dim3(LSEQ/64, LSEQ/128, NHEAD*BATCH), blk, SMEM_SZ>>>(
        pQ,(long long)LSEQ*DKH, pK,(long long)LSEQ*DKH,
        LSEQ, LSEQ, DKH, pS,(long long)LSEQ*LSEQ, nullptr,0, nullptr,
        nullptr,nullptr,nullptr, nullptr,nullptr,nullptr);
    softmax_rows<<<dim3(LSEQ, NHEAD*BATCH), 256>>>(pS, pP);
    // O = P @ Vt^T per (h,b), fp16 out, K clamped to len
    gemm_mma<7,3><<<dim3(DVH/64, LSEQ/128, NHEAD*BATCH), blk, SMEM_SZ>>>(
        pP,(long long)LSEQ*LSEQ, pVt,(long long)DVH*LSEQ,
        LSEQ, DVH, LSEQ, pO,(long long)LSEQ*DVH, nullptr,0, nullptr,
        nullptr,nullptr,nullptr, nullptr,nullptr,nullptr);
    // gate logits: batched over heads, per-head bias, fp16 out
    gemm_mma<3,1><<<dim3(DVH/64, M/128, NHEAD), blk, SMEM_SZ>>>(
        pO,(long long)M*DVH, pWg,(long long)DVH*DMODEL,
        M, DVH, DMODEL, pG,(long long)M*DVH, b_g, DVH, nullptr,
        nullptr,nullptr,nullptr, nullptr,nullptr,nullptr);
    gate_combine<<<(M*DVH/4 + 255)/256, 256>>>(pG, pO, pY);
    // final FC + bias + residual + pad zeroing (fp32 out)
    gemm_mma<4,4><<<dim3(DMODEL/64, M/128, 1), blk, SMEM_SZ>>>(
        pY,0, pWfc,0, M, DMODEL, DVH, out,0, b_fc,0, enc,
        nullptr,nullptr,nullptr, nullptr,nullptr,nullptr);
}

// round 14
// speedup vs baseline: 1.0519x; 1.0519x over previous
#include <cuda_runtime.h>
#include <cuda_fp16.h>
#include <cstdint>

#define BATCH  8
#define LSEQ   1024
#define DMODEL 512
#define NHEAD  8
#define DKH    64
#define DVH    512
#define MTOT   (BATCH*LSEQ)

// ---------------- scratch (static device globals, zero-initialized) ---------
__device__ __align__(256) __half g_ench[MTOT*DMODEL];
__device__ __align__(256) __half g_Wqh [DMODEL*DMODEL];
__device__ __align__(256) __half g_Wkh [DMODEL*DMODEL];
__device__ __align__(256) __half g_Wvh [NHEAD*DVH*DMODEL];
__device__ __align__(256) __half g_Wgh [NHEAD*DVH*DMODEL];
__device__ __align__(256) __half g_Wfch[DMODEL*DVH];
__device__ __align__(256) __half g_Q [NHEAD*MTOT*DKH];       // [h][b][l][dk]
__device__ __align__(256) __half g_K [NHEAD*MTOT*DKH];
__device__ __align__(256) __half g_Vt[NHEAD*BATCH*DVH*LSEQ]; // [h][b][dv][l]
__device__ __align__(256) __half g_S [67108864];             // [hb][q][k] fp16
__device__ __align__(256) __half g_P [67108864];             // softmax(S) fp16
__device__ __align__(256) __half g_O [NHEAD*MTOT*DVH];
__device__ __align__(256) __half g_G [NHEAD*MTOT*DVH];
__device__ __align__(256) __half g_Y [MTOT*DVH];
__device__ int   g_len[BATCH];

// ---------------- helpers ----------------------------------------------------
__device__ __forceinline__ uint32_t smem_u32(const void* p) {
    uint32_t a;
    asm("{ .reg .u64 t; cvta.to.shared.u64 t, %1; cvt.u32.u64 %0, t; }"
        : "=r"(a) : "l"(p));
    return a;
}
__device__ __forceinline__ void cp16(uint32_t s, const void* g) {
    asm volatile("cp.async.cg.shared.global [%0], [%1], 16;" :: "r"(s), "l"(g));
}
__device__ __forceinline__ void ldsm4(uint32_t& r0, uint32_t& r1,
                                      uint32_t& r2, uint32_t& r3, uint32_t a) {
    asm volatile("ldmatrix.sync.aligned.m8n8.x4.shared.b16 {%0,%1,%2,%3}, [%4];"
                 : "=r"(r0), "=r"(r1), "=r"(r2), "=r"(r3) : "r"(a));
}
__device__ __forceinline__ void mma_f16(float& c0, float& c1, float& c2, float& c3,
                                        uint32_t a0, uint32_t a1, uint32_t a2, uint32_t a3,
                                        uint32_t b0, uint32_t b1) {
    asm volatile("mma.sync.aligned.m16n8k16.row.col.f32.f16.f16.f32 "
                 "{%0,%1,%2,%3}, {%4,%5,%6,%7}, {%8,%9}, {%0,%1,%2,%3};"
                 : "+f"(c0), "+f"(c1), "+f"(c2), "+f"(c3)
                 : "r"(a0), "r"(a1), "r"(a2), "r"(a3), "r"(b0), "r"(b1));
}

// ---------------- fp32 -> fp16 conversion of enc + weights -------------------
#define N_ENC (MTOT*DMODEL)
#define N_WQ  (DMODEL*DMODEL)
#define N_WV  (NHEAD*DVH*DMODEL)
__global__ void convert_inputs(const float* __restrict__ enc,
                               const float* __restrict__ wq,
                               const float* __restrict__ wk,
                               const float* __restrict__ wv,
                               const float* __restrict__ wg,
                               const float* __restrict__ wfc) {
    const long long i4 = ((long long)blockIdx.x * 256 + threadIdx.x) * 4;
    const float* src; __half* dst; long long off;
    if      (i4 < N_ENC)                   { src = enc; dst = g_ench; off = i4; }
    else if (i4 < N_ENC + N_WQ)            { src = wq;  dst = g_Wqh;  off = i4 - N_ENC; }
    else if (i4 < N_ENC + 2*N_WQ)          { src = wk;  dst = g_Wkh;  off = i4 - N_ENC - N_WQ; }
    else if (i4 < N_ENC + 2*N_WQ + N_WV)   { src = wv;  dst = g_Wvh;  off = i4 - N_ENC - 2*N_WQ; }
    else if (i4 < N_ENC + 2*N_WQ + 2*N_WV) { src = wg;  dst = g_Wgh;  off = i4 - N_ENC - 2*N_WQ - N_WV; }
    else if (i4 < N_ENC + 3*N_WQ + 2*N_WV) { src = wfc; dst = g_Wfch; off = i4 - N_ENC - 2*N_WQ - 2*N_WV; }
    else return;
    const float4 v = *reinterpret_cast<const float4*>(src + off);
    __half2* d2 = reinterpret_cast<__half2*>(dst + off);
    d2[0] = __floats2half2_rn(v.x, v.y);
    d2[1] = __floats2half2_rn(v.z, v.w);
}

// ---------------- mask prep --------------------------------------------------
__global__ void prep_mask(const unsigned char* __restrict__ mask8) {
    __shared__ int s_violate;
    __shared__ int s_len[BATCH];
    const int t = threadIdx.x;
    if (t == 0) s_violate = 0;
    if (t < BATCH) s_len[t] = LSEQ;
    __syncthreads();
    for (int i = t; i < BATCH*LSEQ - 1; i += blockDim.x) {
        if ((i & (LSEQ-1)) != LSEQ-1) {
            if (mask8[i] != 0 && mask8[i+1] == 0) atomicOr(&s_violate, 1);
        }
    }
    __syncthreads();
    const bool is4 = (s_violate != 0);
    if (!is4) {
        for (int i = t; i < BATCH*LSEQ; i += blockDim.x)
            if (mask8[i] != 0) atomicMin(&s_len[i >> 10], i & (LSEQ-1));
    } else {
        const unsigned int* m32 = reinterpret_cast<const unsigned int*>(mask8);
        for (int i = t; i < BATCH*LSEQ; i += blockDim.x)
            if (m32[i] != 0) atomicMin(&s_len[i >> 10], i & (LSEQ-1));
    }
    __syncthreads();
    if (t < BATCH) g_len[t] = s_len[t];
}

// ---------------- fp16 mma GEMM: C = A @ B^T (round-12 config) ---------------
// BM=BN=128, BK=64 halfs, 256 threads (8 warps, 64x32 warp tiles), 3-stage
// cp.async pipeline, ldmatrix.x4 fragment loads, direct epilogue stores.
#define ASTRH   72
#define ABYTES  (128*ASTRH*2)       // 18432
#define STAGEB  (2*ABYTES)          // 36864
#define SMEM_SZ (3*STAGEB)          // 110592
#define SREG    136

template<int MODE, int SKIP>
__global__ void __launch_bounds__(256, 2)
gemm_mma(const __half* __restrict__ A, long long sA,
         const __half* __restrict__ Bm, long long sB,
         int M, int N, int K,
         void* __restrict__ C, long long sC,
         const float* __restrict__ bias, int sBias,
         const float* __restrict__ resid,
         const __half* B2, const float* bias2, void* C2,
         const __half* B3, const float* bias3, void* C3)
{
    extern __shared__ char dsm[];
    const int tid  = threadIdx.x;
    const int w    = tid >> 5;
    const int lane = tid & 31;
    const int wm   = w & 1;
    const int wn   = w >> 1;
    const int batch = blockIdx.z;
    const int bm = blockIdx.y * 128;

    const __half* Bsrc = Bm;
    const float* biasp = bias;
    void* Cp = C;
    int bn = blockIdx.x * 128;
    int smode = MODE;
    if (MODE == 5) {
        const int bx = blockIdx.x;
        if (bx < 4)      { smode = 0; bn = bx * 128; }
        else if (bx < 8) { smode = 0; bn = (bx-4) * 128; Bsrc = B2; biasp = bias2; Cp = C2; }
        else             { smode = 6; bn = (bx-8) * 128; Bsrc = B3; biasp = bias3; Cp = C3; }
    }

    int Keff = K;
    if (SKIP == 1) {
        if ((bm & (LSEQ-1)) >= g_len[bm >> 10]) return;
    } else if (SKIP == 3) {
        const int L = g_len[batch & (BATCH-1)];
        if (bm >= L) return;
        Keff = (L + 63) & ~63;
    } else if (SKIP == 4) {
        if ((bm & (LSEQ-1)) >= g_len[bm >> 10]) {
            float* Cf = (float*)Cp;
            const float4 z = {0.f, 0.f, 0.f, 0.f};
            for (int i = tid; i < 128*32; i += 256) {
                const int r = i >> 5, c4 = i & 31;
                *reinterpret_cast<float4*>(&Cf[(long long)(bm + r)*N + bn + c4*4]) = z;
            }
            return;
        }
    }

    const __half* Ab = A    + (long long)batch * sA;
    const __half* Bb = Bsrc + (long long)batch * sB;
    const uint32_t smem0 = smem_u32(dsm);
    const int KC = Keff >> 6;

    auto load_stage = [&](int kc) {
        const int st = kc % 3;
        const uint32_t sa = smem0 + st * STAGEB;
        const uint32_t sb = sa + ABYTES;
        const int k0 = kc << 6;
        #pragma unroll
        for (int i = 0; i < 4; i++) {
            const int idx = tid + i * 256;
            const int row = idx >> 3, chk = idx & 7;
            cp16(sa + row*(ASTRH*2) + chk*16,
                 Ab + (long long)(bm + row) * K + k0 + chk*8);
        }
        #pragma unroll
        for (int i = 0; i < 4; i++) {
            const int idx = tid + i * 256;
            const int row = idx >> 3, chk = idx & 7;
            cp16(sb + row*(ASTRH*2) + chk*16,
                 Bb + (long long)(bn + row) * K + k0 + chk*8);
        }
        asm volatile("cp.async.commit_group;" ::: "memory");
    };

    float acc[4][4][4];
    #pragma unroll
    for (int i = 0; i < 4; i++)
        #pragma unroll
        for (int j = 0; j < 4; j++)
            #pragma unroll
            for (int q = 0; q < 4; q++) acc[i][j][q] = 0.f;

    load_stage(0);
    if (KC > 1) load_stage(1);

    const int lrow_a  = lane & 15;
    const int lkoff_a = (lane >> 4) * 8;
    const int lrow_b  = (lane & 7) + ((lane >> 4) << 3);
    const int lkoff_b = (lane & 8) ? 8 : 0;

    for (int kc = 0; kc < KC; kc++) {
        if (kc + 1 < KC) asm volatile("cp.async.wait_group 1;" ::: "memory");
        else             asm volatile("cp.async.wait_group 0;" ::: "memory");
        __syncthreads();
        if (kc + 2 < KC) load_stage(kc + 2);

        const int st = kc % 3;
        const uint32_t Abase = smem0 + st * STAGEB;
        const uint32_t Bbase = Abase + ABYTES;

        #pragma unroll
        for (int ks = 0; ks < 4; ks++) {
            uint32_t af[4][4];
            #pragma unroll
            for (int mt = 0; mt < 4; mt++) {
                const uint32_t addr = Abase +
                    ((wm*64 + mt*16 + lrow_a)*ASTRH + ks*16 + lkoff_a) * 2;
                ldsm4(af[mt][0], af[mt][1], af[mt][2], af[mt][3], addr);
            }
            uint32_t bf[4][2];
            #pragma unroll
            for (int np = 0; np < 2; np++) {
                const uint32_t addr = Bbase +
                    ((wn*32 + np*16 + lrow_b)*ASTRH + ks*16 + lkoff_b) * 2;
                ldsm4(bf[np*2][0], bf[np*2][1], bf[np*2+1][0], bf[np*2+1][1], addr);
            }
            #pragma unroll
            for (int mt = 0; mt < 4; mt++)
                #pragma unroll
                for (int nt = 0; nt < 4; nt++)
                    mma_f16(acc[mt][nt][0], acc[mt][nt][1], acc[mt][nt][2], acc[mt][nt][3],
                            af[mt][0], af[mt][1], af[mt][2], af[mt][3],
                            bf[nt][0], bf[nt][1]);
        }
    }

    if (MODE == 5 && smode == 6) {   // V transposed store via smem staging
        __syncthreads();
        __half* stg = reinterpret_cast<__half*>(dsm);
        #pragma unroll
        for (int mt = 0; mt < 4; mt++) {
            #pragma unroll
            for (int half_ = 0; half_ < 2; half_++) {
                const int ml = wm*64 + mt*16 + (lane >> 2) + half_*8;
                #pragma unroll
                for (int nt = 0; nt < 4; nt++) {
                    const int nl = wn*32 + nt*8 + (lane & 3)*2;
                    const float2 bv = *reinterpret_cast<const float2*>(&biasp[bn + nl]);
                    stg[nl*SREG + ml]     = __float2half_rn(acc[mt][nt][half_*2 + 0] + bv.x);
                    stg[(nl+1)*SREG + ml] = __float2half_rn(acc[mt][nt][half_*2 + 1] + bv.y);
                }
            }
        }
        __syncthreads();
        const int h = bn >> 9, dv0 = bn & 511;
        const int b = bm >> 10, l0 = bm & (LSEQ-1);
        __half* Vt = (__half*)Cp + (((long long)h*BATCH + b)*DVH + dv0)*LSEQ + l0;
        #pragma unroll
        for (int i = 0; i < 8; i++) {
            const int u = tid + i*256;
            const int dv = u >> 4, lc = u & 15;
            const uint4 o = *reinterpret_cast<const uint4*>(&stg[dv*SREG + lc*8]);
            *reinterpret_cast<uint4*>(&Vt[(long long)dv*LSEQ + lc*8]) = o;
        }
        return;
    }

    #pragma unroll
    for (int mt = 0; mt < 4; mt++) {
        const int r0 = bm + wm*64 + mt*16 + (lane >> 2);
        #pragma unroll
        for (int half_ = 0; half_ < 2; half_++) {
            const int m = r0 + half_*8;
            const int b_idx = m >> 10, l_idx = m & (LSEQ-1);
            #pragma unroll
            for (int nt = 0; nt < 4; nt++) {
                const int n = bn + wn*32 + nt*8 + (lane & 3)*2;
                const float v0 = acc[mt][nt][half_*2 + 0];
                const float v1 = acc[mt][nt][half_*2 + 1];
                if (MODE == 5) {
                    const float2 bv = *reinterpret_cast<const float2*>(&biasp[n]);
                    const int h = n >> 6, d = n & 63;
                    __half* Ch = (__half*)Cp;
                    *reinterpret_cast<__half2*>(&Ch[((long long)h*MTOT + m)*DKH + d]) =
                        __floats2half2_rn(v0 + bv.x, v1 + bv.y);
                } else if (MODE == 7) {
                    __half* Ch = (__half*)Cp;
                    *reinterpret_cast<__half2*>(
                        &Ch[(long long)batch*sC + (long long)m*N + n]) =
                        __floats2half2_rn(v0, v1);
                } else if (MODE == 3) {
                    const float2 bv = *reinterpret_cast<const float2*>(
                        &biasp[(long long)batch*sBias + n]);
                    __half* Ch = (__half*)Cp;
                    *reinterpret_cast<__half2*>(
                        &Ch[(long long)batch*sC + (long long)m*N + n]) =
                        __floats2half2_rn(v0 + bv.x, v1 + bv.y);
                } else { // MODE 4
                    float* Cf = (float*)Cp;
                    float2 o;
                    if (l_idx >= g_len[b_idx]) { o.x = 0.f; o.y = 0.f; }
                    else {
                        const float2 bv = *reinterpret_cast<const float2*>(&biasp[n]);
                        const float2 rv = *reinterpret_cast<const float2*>(
                            &resid[(long long)m*N + n]);
                        o.x = v0 + bv.x + rv.x;
                        o.y = v1 + bv.y + rv.y;
                    }
                    *reinterpret_cast<float2*>(&Cf[(long long)m*N + n]) = o;
                }
            }
        }
    }
}

// ---------------- fused S = Q@K^T strip + softmax -> P ------------------------
// Grid (8 q-tiles, 64 hb). One CTA owns a 128-row strip of one (h,b):
// Q tile loaded to smem ONCE; bn-loop over ceil(L/128) K-tiles with
// double-buffered cp.async (K j+1 loads during compute of j); raw fp16 S tiles
// written to global. Then (same CTA, after __syncthreads: CTA-coherent via L2)
// each warp pulls 16 rows of its own S strip into registers and applies the
// round-12 softmax arithmetic exactly, writing P (zeros beyond len).
#define QK_Q    0
#define QK_K0   ABYTES
#define QK_SMEM (3*ABYTES)          // 55296

__global__ void __launch_bounds__(256, 2)
qk_softmax(const __half* __restrict__ Q, const __half* __restrict__ Kg,
           __half* __restrict__ S, __half* __restrict__ P)
{
    extern __shared__ char dsm[];
    const int tid = threadIdx.x, w = tid >> 5, lane = tid & 31;
    const int wm = w & 1, wn = w >> 1;
    const int hb = blockIdx.y;
    const int L  = g_len[hb & (BATCH-1)];
    const int bm = blockIdx.x * 128;
    if (bm >= L) return;                    // padded strips: S/P rows unused/0

    const __half* Qg = Q  + ((long long)hb*LSEQ + bm) * DKH;
    const __half* Kb = Kg + (long long)hb*LSEQ*DKH;
    __half* Sp = S + (long long)hb*LSEQ*LSEQ;
    __half* Pp = P + (long long)hb*LSEQ*LSEQ;

    const uint32_t smem0 = smem_u32(dsm);
    const int nbt = (L + 127) >> 7;

    // Q tile: 128 rows x 64 halfs (one group with K0)
    {
        #pragma unroll
        for (int i = 0; i < 4; i++) {
            const int idx = tid + i*256;
            const int row = idx >> 3, chk = idx & 7;
            cp16(smem0 + QK_Q + row*(ASTRH*2) + chk*16,
                 Qg + (long long)row*DKH + chk*8);
        }
    }
    auto load_k = [&](int j) {
        const uint32_t sk = smem0 + QK_K0 + (j & 1)*ABYTES;
        const int kr = j << 7;
        #pragma unroll
        for (int i = 0; i < 4; i++) {
            const int idx = tid + i*256;
            const int row = idx >> 3, chk = idx & 7;
            cp16(sk + row*(ASTRH*2) + chk*16,
                 Kb + (long long)(kr + row)*DKH + chk*8);
        }
        asm volatile("cp.async.commit_group;" ::: "memory");
    };
    load_k(0);                                       // group 0: Q + K0

    const int lrow_a  = lane & 15;
    const int lkoff_a = (lane >> 4) * 8;
    const int lrow_b  = (lane & 7) + ((lane >> 4) << 3);
    const int lkoff_b = (lane & 8) ? 8 : 0;

    for (int j = 0; j < nbt; j++) {
        asm volatile("cp.async.wait_group 0;" ::: "memory");
        __syncthreads();
        if (j + 1 < nbt) load_k(j + 1);              // other buffer; overlaps

        float acc[4][4][4];
        #pragma unroll
        for (int i = 0; i < 4; i++)
            #pragma unroll
            for (int jj = 0; jj < 4; jj++)
                #pragma unroll
                for (int q = 0; q < 4; q++) acc[i][jj][q] = 0.f;

        const uint32_t Abase = smem0 + QK_Q;
        const uint32_t Bbase = smem0 + QK_K0 + (j & 1)*ABYTES;
        #pragma unroll
        for (int ks = 0; ks < 4; ks++) {
            uint32_t af[4][4];
            #pragma unroll
            for (int mt = 0; mt < 4; mt++) {
                const uint32_t addr = Abase +
                    ((wm*64 + mt*16 + lrow_a)*ASTRH + ks*16 + lkoff_a) * 2;
                ldsm4(af[mt][0], af[mt][1], af[mt][2], af[mt][3], addr);
            }
            uint32_t bf[4][2];
            #pragma unroll
            for (int np = 0; np < 2; np++) {
                const uint32_t addr = Bbase +
                    ((wn*32 + np*16 + lrow_b)*ASTRH + ks*16 + lkoff_b) * 2;
                ldsm4(bf[np*2][0], bf[np*2][1], bf[np*2+1][0], bf[np*2+1][1], addr);
            }
            #pragma unroll
            for (int mt = 0; mt < 4; mt++)
                #pragma unroll
                for (int nt = 0; nt < 4; nt++)
                    mma_f16(acc[mt][nt][0], acc[mt][nt][1], acc[mt][nt][2], acc[mt][nt][3],
                            af[mt][0], af[mt][1], af[mt][2], af[mt][3],
                            bf[nt][0], bf[nt][1]);
        }

        // raw S tile store (fp16)
        const int cn0 = (j << 7) + wn*32 + (lane & 3)*2;
        #pragma unroll
        for (int mt = 0; mt < 4; mt++) {
            #pragma unroll
            for (int half_ = 0; half_ < 2; half_++) {
                const int m = bm + wm*64 + mt*16 + (lane >> 2) + half_*8;
                #pragma unroll
                for (int nt = 0; nt < 4; nt++) {
                    *reinterpret_cast<__half2*>(&Sp[(long long)m*LSEQ + cn0 + nt*8]) =
                        __floats2half2_rn(acc[mt][nt][half_*2 + 0],
                                          acc[mt][nt][half_*2 + 1]);
                }
            }
        }
    }

    __syncthreads();   // all S writes visible CTA-wide (global, block scope)

    // -------- softmax over the strip: warp w handles rows w*16 .. w*16+15 ----
    const float NEG = -1e30f;
    for (int i = 0; i < 16; i++) {
        const int m = bm + w*16 + i;
        if (m >= L) continue;                        // P rows stay 0
        const uint4* rp = reinterpret_cast<const uint4*>(Sp + (long long)m*LSEQ);
        uint4 v[4];
        #pragma unroll
        for (int it = 0; it < 4; it++) v[it] = rp[lane + it*32];

        float mx = NEG;
        #pragma unroll
        for (int it = 0; it < 4; it++) {
            const int c0 = (lane + it*32)*8;
            const uint32_t* pw = reinterpret_cast<const uint32_t*>(&v[it]);
            #pragma unroll
            for (int q = 0; q < 4; q++) {
                const float2 f = __half22float2(
                    *reinterpret_cast<const __half2*>(&pw[q]));
                const int c = c0 + q*2;
                mx = fmaxf(mx, (c   < L) ? f.x : NEG);
                mx = fmaxf(mx, (c+1 < L) ? f.y : NEG);
            }
        }
        #pragma unroll
        for (int o = 16; o; o >>= 1) mx = fmaxf(mx, __shfl_xor_sync(~0u, mx, o));
        mx *= 0.125f;

        float s = 0.f;
        #pragma unroll
        for (int it = 0; it < 4; it++) {
            const int c0 = (lane + it*32)*8;
            const uint32_t* pw = reinterpret_cast<const uint32_t*>(&v[it]);
            #pragma unroll
            for (int q = 0; q < 4; q++) {
                const float2 f = __half22float2(
                    *reinterpret_cast<const __half2*>(&pw[q]));
                const int c = c0 + q*2;
                if (c   < L) s += __expf(f.x*0.125f - mx);
                if (c+1 < L) s += __expf(f.y*0.125f - mx);
            }
        }
        #pragma unroll
        for (int o = 16; o; o >>= 1) s += __shfl_xor_sync(~0u, s, o);
        const float inv = 1.f / s;

        uint4* op = reinterpret_cast<uint4*>(Pp + (long long)m*LSEQ);
        #pragma unroll
        for (int it = 0; it < 4; it++) {
            const int c0 = (lane + it*32)*8;
            const uint32_t* pw = reinterpret_cast<const uint32_t*>(&v[it]);
            uint4 o;
            uint32_t* ow = reinterpret_cast<uint32_t*>(&o);
            #pragma unroll
            for (int q = 0; q < 4; q++) {
                const float2 f = __half22float2(
                    *reinterpret_cast<const __half2*>(&pw[q]));
                const int c = c0 + q*2;
                const float p0 = (c   < L) ? __expf(f.x*0.125f - mx)*inv : 0.f;
                const float p1 = (c+1 < L) ? __expf(f.y*0.125f - mx)*inv : 0.f;
                const __half2 h = __floats2half2_rn(p0, p1);
                ow[q] = *reinterpret_cast<const uint32_t*>(&h);
            }
            op[lane + it*32] = o;
        }
    }
}

// ---------------- head-gate softmax + weighted combine (fp16 in/out) ---------
__global__ void gate_combine(const __half* __restrict__ G,
                             const __half* __restrict__ O,
                             __half* __restrict__ Y) {
    const int HS4 = MTOT*DVH/4;
    const int i = blockIdx.x * blockDim.x + threadIdx.x;
    if (i >= HS4) return;
    const int m = i >> 7;
    if ((m & (LSEQ-1)) >= g_len[m >> 10]) return;

    const uint2* G4 = reinterpret_cast<const uint2*>(G);
    const uint2* O4 = reinterpret_cast<const uint2*>(O);
    float g[NHEAD][4];
    float mx0 = -1e30f, mx1 = -1e30f, mx2 = -1e30f, mx3 = -1e30f;
    #pragma unroll
    for (int h = 0; h < NHEAD; h++) {
        const uint2 u = G4[(long long)h*HS4 + i];
        const float2 a = __half22float2(*reinterpret_cast<const __half2*>(&u.x));
        const float2 b = __half22float2(*reinterpret_cast<const __half2*>(&u.y));
        g[h][0] = a.x; g[h][1] = a.y; g[h][2] = b.x; g[h][3] = b.y;
        mx0 = fmaxf(mx0, a.x); mx1 = fmaxf(mx1, a.y);
        mx2 = fmaxf(mx2, b.x); mx3 = fmaxf(mx3, b.y);
    }
    float acc0=0, acc1=0, acc2=0, acc3=0, s0=0, s1=0, s2=0, s3=0;
    #pragma unroll
    for (int h = 0; h < NHEAD; h++) {
        const uint2 u = O4[(long long)h*HS4 + i];
        const float2 a = __half22float2(*reinterpret_cast<const __half2*>(&u.x));
        const float2 b = __half22float2(*reinterpret_cast<const __half2*>(&u.y));
        const float e0 = __expf(g[h][0] - mx0), e1 = __expf(g[h][1] - mx1);
        const float e2 = __expf(g[h][2] - mx2), e3 = __expf(g[h][3] - mx3);
        s0 += e0; s1 += e1; s2 += e2; s3 += e3;
        acc0 += e0*a.x; acc1 += e1*a.y; acc2 += e2*b.x; acc3 += e3*b.y;
    }
    uint2 o;
    *reinterpret_cast<__half2*>(&o.x) = __floats2half2_rn(acc0/s0, acc1/s1);
    *reinterpret_cast<__half2*>(&o.y) = __floats2half2_rn(acc2/s2, acc3/s3);
    reinterpret_cast<uint2*>(Y)[i] = o;
}

// ---------------- launch ------------------------------------------------------
extern "C" void kernel_launch(void* const* d_in, const int* in_sizes, int n_in,
                              void* d_out, int out_size) {
    const float*         enc  = (const float*)d_in[0];
    const unsigned char* npm  = (const unsigned char*)d_in[1];
    const float* w_q  = (const float*)d_in[3];
    const float* b_q  = (const float*)d_in[4];
    const float* w_k  = (const float*)d_in[5];
    const float* b_k  = (const float*)d_in[6];
    const float* w_v  = (const float*)d_in[7];
    const float* b_v  = (const float*)d_in[8];
    const float* w_g  = (const float*)d_in[9];
    const float* b_g  = (const float*)d_in[10];
    const float* w_fc = (const float*)d_in[11];
    const float* b_fc = (const float*)d_in[12];
    float* out = (float*)d_out;

    __half *pEnc,*pWq,*pWk,*pWv,*pWg,*pWfc,*pQ,*pK,*pVt,*pS,*pP,*pO,*pG,*pY;
    cudaGetSymbolAddress((void**)&pEnc, g_ench);
    cudaGetSymbolAddress((void**)&pWq,  g_Wqh);
    cudaGetSymbolAddress((void**)&pWk,  g_Wkh);
    cudaGetSymbolAddress((void**)&pWv,  g_Wvh);
    cudaGetSymbolAddress((void**)&pWg,  g_Wgh);
    cudaGetSymbolAddress((void**)&pWfc, g_Wfch);
    cudaGetSymbolAddress((void**)&pQ,   g_Q);
    cudaGetSymbolAddress((void**)&pK,   g_K);
    cudaGetSymbolAddress((void**)&pVt,  g_Vt);
    cudaGetSymbolAddress((void**)&pS,   g_S);
    cudaGetSymbolAddress((void**)&pP,   g_P);
    cudaGetSymbolAddress((void**)&pO,   g_O);
    cudaGetSymbolAddress((void**)&pG,   g_G);
    cudaGetSymbolAddress((void**)&pY,   g_Y);

    cudaFuncSetAttribute(gemm_mma<5,1>, cudaFuncAttributeMaxDynamicSharedMemorySize, SMEM_SZ);
    cudaFuncSetAttribute(gemm_mma<7,3>, cudaFuncAttributeMaxDynamicSharedMemorySize, SMEM_SZ);
    cudaFuncSetAttribute(gemm_mma<3,1>, cudaFuncAttributeMaxDynamicSharedMemorySize, SMEM_SZ);
    cudaFuncSetAttribute(gemm_mma<4,4>, cudaFuncAttributeMaxDynamicSharedMemorySize, SMEM_SZ);
    cudaFuncSetAttribute(qk_softmax,    cudaFuncAttributeMaxDynamicSharedMemorySize, QK_SMEM);

    const int M = MTOT;
    dim3 blk(256);

    convert_inputs<<<(N_ENC + 3*N_WQ + 2*N_WV) / 1024, 256>>>(enc, w_q, w_k, w_v, w_g, w_fc);
    prep_mask<<<1, 256>>>(npm);

    // Fused Q/K/V projections (fp16): Q,K -> [h][m][dk]; V -> Vt[h][b][dv][l]
    gemm_mma<5,1><<<dim3(40, M/128, 1), blk, SMEM_SZ>>>(
        pEnc,0, pWq,0, M, NHEAD*DKH, DMODEL, pQ,0, b_q,0, nullptr,
        pWk, b_k, pK, pWv, b_v, pVt);
    // Fused S strip GEMM + softmax -> P
    qk_softmax<<<dim3(LSEQ/128, NHEAD*BATCH), blk, QK_SMEM>>>(pQ, pK, pS, pP);
    // O = P @ Vt^T per (h,b), fp16 out, K clamped to len
    gemm_mma<7,3><<<dim3(DVH/128, LSEQ/128, NHEAD*BATCH), blk, SMEM_SZ>>>(
        pP,(long long)LSEQ*LSEQ, pVt,(long long)DVH*LSEQ,
        LSEQ, DVH, LSEQ, pO,(long long)LSEQ*DVH, nullptr,0, nullptr,
        nullptr,nullptr,nullptr, nullptr,nullptr,nullptr);
    // gate logits: batched over heads, per-head bias, fp16 out
    gemm_mma<3,1><<<dim3(DVH/128, M/128, NHEAD), blk, SMEM_SZ>>>(
        pO,(long long)M*DVH, pWg,(long long)DVH*DMODEL,
        M, DVH, DMODEL, pG,(long long)M*DVH, b_g, DVH, nullptr,
        nullptr,nullptr,nullptr, nullptr,nullptr,nullptr);
    gate_combine<<<(M*DVH/4 + 255)/256, 256>>>(pG, pO, pY);
    // final FC + bias + residual + pad zeroing (fp32 out)
    gemm_mma<4,4><<<dim3(DMODEL/128, M/128, 1), blk, SMEM_SZ>>>(
        pY,0, pWfc,0, M, DMODEL, DVH, out,0, b_fc,0, enc,
        nullptr,nullptr,nullptr, nullptr,nullptr,nullptr);
}

// round 15
// speedup vs baseline: 1.0841x; 1.0307x over previous
#include <cuda_runtime.h>
#include <cuda_fp16.h>
#include <cstdint>

#define BATCH  8
#define LSEQ   1024
#define DMODEL 512
#define NHEAD  8
#define DKH    64
#define DVH    512
#define MTOT   (BATCH*LSEQ)

// ---------------- scratch (static device globals, zero-initialized) ---------
__device__ __align__(256) __half g_ench[MTOT*DMODEL];
__device__ __align__(256) __half g_Wqh [DMODEL*DMODEL];
__device__ __align__(256) __half g_Wkh [DMODEL*DMODEL];
__device__ __align__(256) __half g_Wvh [NHEAD*DVH*DMODEL];
__device__ __align__(256) __half g_Wgh [NHEAD*DVH*DMODEL];
__device__ __align__(256) __half g_Wfch[DMODEL*DVH];
__device__ __align__(256) __half g_Q [NHEAD*MTOT*DKH];       // [h][b][l][dk]
__device__ __align__(256) __half g_K [NHEAD*MTOT*DKH];
__device__ __align__(256) __half g_Vt[NHEAD*BATCH*DVH*LSEQ]; // [h][b][dv][l]
__device__ __align__(256) __half g_S [67108864];             // [hb][q][k] fp16
__device__ __align__(256) __half g_P [67108864];             // softmax(S) fp16
__device__ __align__(256) __half g_O [NHEAD*MTOT*DVH];
__device__ __align__(256) __half g_G [NHEAD*MTOT*DVH];
__device__ __align__(256) __half g_Y [MTOT*DVH];
__device__ int   g_len[BATCH];

// ---------------- helpers ----------------------------------------------------
__device__ __forceinline__ uint32_t smem_u32(const void* p) {
    uint32_t a;
    asm("{ .reg .u64 t; cvta.to.shared.u64 t, %1; cvt.u32.u64 %0, t; }"
        : "=r"(a) : "l"(p));
    return a;
}
__device__ __forceinline__ void cp16(uint32_t s, const void* g) {
    asm volatile("cp.async.cg.shared.global [%0], [%1], 16;" :: "r"(s), "l"(g));
}
__device__ __forceinline__ void ldsm4(uint32_t& r0, uint32_t& r1,
                                      uint32_t& r2, uint32_t& r3, uint32_t a) {
    asm volatile("ldmatrix.sync.aligned.m8n8.x4.shared.b16 {%0,%1,%2,%3}, [%4];"
                 : "=r"(r0), "=r"(r1), "=r"(r2), "=r"(r3) : "r"(a));
}
__device__ __forceinline__ void mma_f16(float& c0, float& c1, float& c2, float& c3,
                                        uint32_t a0, uint32_t a1, uint32_t a2, uint32_t a3,
                                        uint32_t b0, uint32_t b1) {
    asm volatile("mma.sync.aligned.m16n8k16.row.col.f32.f16.f16.f32 "
                 "{%0,%1,%2,%3}, {%4,%5,%6,%7}, {%8,%9}, {%0,%1,%2,%3};"
                 : "+f"(c0), "+f"(c1), "+f"(c2), "+f"(c3)
                 : "r"(a0), "r"(a1), "r"(a2), "r"(a3), "r"(b0), "r"(b1));
}

// ---------------- fp32 -> fp16 conversion of enc + weights -------------------
#define N_ENC (MTOT*DMODEL)
#define N_WQ  (DMODEL*DMODEL)
#define N_WV  (NHEAD*DVH*DMODEL)
__global__ void convert_inputs(const float* __restrict__ enc,
                               const float* __restrict__ wq,
                               const float* __restrict__ wk,
                               const float* __restrict__ wv,
                               const float* __restrict__ wg,
                               const float* __restrict__ wfc) {
    const long long i4 = ((long long)blockIdx.x * 256 + threadIdx.x) * 4;
    const float* src; __half* dst; long long off;
    if      (i4 < N_ENC)                   { src = enc; dst = g_ench; off = i4; }
    else if (i4 < N_ENC + N_WQ)            { src = wq;  dst = g_Wqh;  off = i4 - N_ENC; }
    else if (i4 < N_ENC + 2*N_WQ)          { src = wk;  dst = g_Wkh;  off = i4 - N_ENC - N_WQ; }
    else if (i4 < N_ENC + 2*N_WQ + N_WV)   { src = wv;  dst = g_Wvh;  off = i4 - N_ENC - 2*N_WQ; }
    else if (i4 < N_ENC + 2*N_WQ + 2*N_WV) { src = wg;  dst = g_Wgh;  off = i4 - N_ENC - 2*N_WQ - N_WV; }
    else if (i4 < N_ENC + 3*N_WQ + 2*N_WV) { src = wfc; dst = g_Wfch; off = i4 - N_ENC - 2*N_WQ - 2*N_WV; }
    else return;
    const float4 v = *reinterpret_cast<const float4*>(src + off);
    __half2* d2 = reinterpret_cast<__half2*>(dst + off);
    d2[0] = __floats2half2_rn(v.x, v.y);
    d2[1] = __floats2half2_rn(v.z, v.w);
}

// ---------------- mask prep --------------------------------------------------
__global__ void prep_mask(const unsigned char* __restrict__ mask8) {
    __shared__ int s_violate;
    __shared__ int s_len[BATCH];
    const int t = threadIdx.x;
    if (t == 0) s_violate = 0;
    if (t < BATCH) s_len[t] = LSEQ;
    __syncthreads();
    for (int i = t; i < BATCH*LSEQ - 1; i += blockDim.x) {
        if ((i & (LSEQ-1)) != LSEQ-1) {
            if (mask8[i] != 0 && mask8[i+1] == 0) atomicOr(&s_violate, 1);
        }
    }
    __syncthreads();
    const bool is4 = (s_violate != 0);
    if (!is4) {
        for (int i = t; i < BATCH*LSEQ; i += blockDim.x)
            if (mask8[i] != 0) atomicMin(&s_len[i >> 10], i & (LSEQ-1));
    } else {
        const unsigned int* m32 = reinterpret_cast<const unsigned int*>(mask8);
        for (int i = t; i < BATCH*LSEQ; i += blockDim.x)
            if (m32[i] != 0) atomicMin(&s_len[i >> 10], i & (LSEQ-1));
    }
    __syncthreads();
    if (t < BATCH) g_len[t] = s_len[t];
}

// ---------------- fp16 mma GEMM: C = A @ B^T (round-12 config) ---------------
#define ASTRH   72
#define ABYTES  (128*ASTRH*2)       // 18432
#define STAGEB  (2*ABYTES)          // 36864
#define SMEM_SZ (3*STAGEB)          // 110592
#define SREG    136

template<int MODE, int SKIP>
__global__ void __launch_bounds__(256, 2)
gemm_mma(const __half* __restrict__ A, long long sA,
         const __half* __restrict__ Bm, long long sB,
         int M, int N, int K,
         void* __restrict__ C, long long sC,
         const float* __restrict__ bias, int sBias,
         const float* __restrict__ resid,
         const __half* B2, const float* bias2, void* C2,
         const __half* B3, const float* bias3, void* C3)
{
    extern __shared__ char dsm[];
    const int tid  = threadIdx.x;
    const int w    = tid >> 5;
    const int lane = tid & 31;
    const int wm   = w & 1;
    const int wn   = w >> 1;
    const int batch = blockIdx.z;
    const int bm = blockIdx.y * 128;

    const __half* Bsrc = Bm;
    const float* biasp = bias;
    void* Cp = C;
    int bn = blockIdx.x * 128;
    int smode = MODE;
    if (MODE == 5) {
        const int bx = blockIdx.x;
        if (bx < 4)      { smode = 0; bn = bx * 128; }
        else if (bx < 8) { smode = 0; bn = (bx-4) * 128; Bsrc = B2; biasp = bias2; Cp = C2; }
        else             { smode = 6; bn = (bx-8) * 128; Bsrc = B3; biasp = bias3; Cp = C3; }
    }

    int Keff = K;
    if (SKIP == 1) {
        if ((bm & (LSEQ-1)) >= g_len[bm >> 10]) return;
    } else if (SKIP == 3) {
        const int L = g_len[batch & (BATCH-1)];
        if (bm >= L) return;
        Keff = (L + 63) & ~63;
    } else if (SKIP == 4) {
        if ((bm & (LSEQ-1)) >= g_len[bm >> 10]) {
            float* Cf = (float*)Cp;
            const float4 z = {0.f, 0.f, 0.f, 0.f};
            for (int i = tid; i < 128*32; i += 256) {
                const int r = i >> 5, c4 = i & 31;
                *reinterpret_cast<float4*>(&Cf[(long long)(bm + r)*N + bn + c4*4]) = z;
            }
            return;
        }
    }

    const __half* Ab = A    + (long long)batch * sA;
    const __half* Bb = Bsrc + (long long)batch * sB;
    const uint32_t smem0 = smem_u32(dsm);
    const int KC = Keff >> 6;

    auto load_stage = [&](int kc) {
        const int st = kc % 3;
        const uint32_t sa = smem0 + st * STAGEB;
        const uint32_t sb = sa + ABYTES;
        const int k0 = kc << 6;
        #pragma unroll
        for (int i = 0; i < 4; i++) {
            const int idx = tid + i * 256;
            const int row = idx >> 3, chk = idx & 7;
            cp16(sa + row*(ASTRH*2) + chk*16,
                 Ab + (long long)(bm + row) * K + k0 + chk*8);
        }
        #pragma unroll
        for (int i = 0; i < 4; i++) {
            const int idx = tid + i * 256;
            const int row = idx >> 3, chk = idx & 7;
            cp16(sb + row*(ASTRH*2) + chk*16,
                 Bb + (long long)(bn + row) * K + k0 + chk*8);
        }
        asm volatile("cp.async.commit_group;" ::: "memory");
    };

    float acc[4][4][4];
    #pragma unroll
    for (int i = 0; i < 4; i++)
        #pragma unroll
        for (int j = 0; j < 4; j++)
            #pragma unroll
            for (int q = 0; q < 4; q++) acc[i][j][q] = 0.f;

    load_stage(0);
    if (KC > 1) load_stage(1);

    const int lrow_a  = lane & 15;
    const int lkoff_a = (lane >> 4) * 8;
    const int lrow_b  = (lane & 7) + ((lane >> 4) << 3);
    const int lkoff_b = (lane & 8) ? 8 : 0;

    for (int kc = 0; kc < KC; kc++) {
        if (kc + 1 < KC) asm volatile("cp.async.wait_group 1;" ::: "memory");
        else             asm volatile("cp.async.wait_group 0;" ::: "memory");
        __syncthreads();
        if (kc + 2 < KC) load_stage(kc + 2);

        const int st = kc % 3;
        const uint32_t Abase = smem0 + st * STAGEB;
        const uint32_t Bbase = Abase + ABYTES;

        #pragma unroll
        for (int ks = 0; ks < 4; ks++) {
            uint32_t af[4][4];
            #pragma unroll
            for (int mt = 0; mt < 4; mt++) {
                const uint32_t addr = Abase +
                    ((wm*64 + mt*16 + lrow_a)*ASTRH + ks*16 + lkoff_a) * 2;
                ldsm4(af[mt][0], af[mt][1], af[mt][2], af[mt][3], addr);
            }
            uint32_t bf[4][2];
            #pragma unroll
            for (int np = 0; np < 2; np++) {
                const uint32_t addr = Bbase +
                    ((wn*32 + np*16 + lrow_b)*ASTRH + ks*16 + lkoff_b) * 2;
                ldsm4(bf[np*2][0], bf[np*2][1], bf[np*2+1][0], bf[np*2+1][1], addr);
            }
            #pragma unroll
            for (int mt = 0; mt < 4; mt++)
                #pragma unroll
                for (int nt = 0; nt < 4; nt++)
                    mma_f16(acc[mt][nt][0], acc[mt][nt][1], acc[mt][nt][2], acc[mt][nt][3],
                            af[mt][0], af[mt][1], af[mt][2], af[mt][3],
                            bf[nt][0], bf[nt][1]);
        }
    }

    if (MODE == 5 && smode == 6) {   // V transposed store via smem staging
        __syncthreads();
        __half* stg = reinterpret_cast<__half*>(dsm);
        #pragma unroll
        for (int mt = 0; mt < 4; mt++) {
            #pragma unroll
            for (int half_ = 0; half_ < 2; half_++) {
                const int ml = wm*64 + mt*16 + (lane >> 2) + half_*8;
                #pragma unroll
                for (int nt = 0; nt < 4; nt++) {
                    const int nl = wn*32 + nt*8 + (lane & 3)*2;
                    const float2 bv = *reinterpret_cast<const float2*>(&biasp[bn + nl]);
                    stg[nl*SREG + ml]     = __float2half_rn(acc[mt][nt][half_*2 + 0] + bv.x);
                    stg[(nl+1)*SREG + ml] = __float2half_rn(acc[mt][nt][half_*2 + 1] + bv.y);
                }
            }
        }
        __syncthreads();
        const int h = bn >> 9, dv0 = bn & 511;
        const int b = bm >> 10, l0 = bm & (LSEQ-1);
        __half* Vt = (__half*)Cp + (((long long)h*BATCH + b)*DVH + dv0)*LSEQ + l0;
        #pragma unroll
        for (int i = 0; i < 8; i++) {
            const int u = tid + i*256;
            const int dv = u >> 4, lc = u & 15;
            const uint4 o = *reinterpret_cast<const uint4*>(&stg[dv*SREG + lc*8]);
            *reinterpret_cast<uint4*>(&Vt[(long long)dv*LSEQ + lc*8]) = o;
        }
        return;
    }

    #pragma unroll
    for (int mt = 0; mt < 4; mt++) {
        const int r0 = bm + wm*64 + mt*16 + (lane >> 2);
        #pragma unroll
        for (int half_ = 0; half_ < 2; half_++) {
            const int m = r0 + half_*8;
            const int b_idx = m >> 10, l_idx = m & (LSEQ-1);
            #pragma unroll
            for (int nt = 0; nt < 4; nt++) {
                const int n = bn + wn*32 + nt*8 + (lane & 3)*2;
                const float v0 = acc[mt][nt][half_*2 + 0];
                const float v1 = acc[mt][nt][half_*2 + 1];
                if (MODE == 5) {
                    const float2 bv = *reinterpret_cast<const float2*>(&biasp[n]);
                    const int h = n >> 6, d = n & 63;
                    __half* Ch = (__half*)Cp;
                    *reinterpret_cast<__half2*>(&Ch[((long long)h*MTOT + m)*DKH + d]) =
                        __floats2half2_rn(v0 + bv.x, v1 + bv.y);
                } else if (MODE == 7) {
                    __half* Ch = (__half*)Cp;
                    *reinterpret_cast<__half2*>(
                        &Ch[(long long)batch*sC + (long long)m*N + n]) =
                        __floats2half2_rn(v0, v1);
                } else if (MODE == 3) {
                    const float2 bv = *reinterpret_cast<const float2*>(
                        &biasp[(long long)batch*sBias + n]);
                    __half* Ch = (__half*)Cp;
                    *reinterpret_cast<__half2*>(
                        &Ch[(long long)batch*sC + (long long)m*N + n]) =
                        __floats2half2_rn(v0 + bv.x, v1 + bv.y);
                } else { // MODE 4
                    float* Cf = (float*)Cp;
                    float2 o;
                    if (l_idx >= g_len[b_idx]) { o.x = 0.f; o.y = 0.f; }
                    else {
                        const float2 bv = *reinterpret_cast<const float2*>(&biasp[n]);
                        const float2 rv = *reinterpret_cast<const float2*>(
                            &resid[(long long)m*N + n]);
                        o.x = v0 + bv.x + rv.x;
                        o.y = v1 + bv.y + rv.y;
                    }
                    *reinterpret_cast<float2*>(&Cf[(long long)m*N + n]) = o;
                }
            }
        }
    }
}

// ---------------- fused S = Q@K^T strip + softmax -> P ------------------------
// Grid (8 q-tiles, 64 hb). After the tiled GEMM, S cols [L,1024) of the strip
// are filled with -60000h (GEMM leaves exactly 0 there; sentinel makes exp
// underflow to exactly 0). Softmax phase is then mask-free:
//   pass1 pure __hmax2 (mx bit-identical: sentinel never wins),
//   pass2 single __expf pass, e packed back into the same registers,
//   pass3 decode * inv (fp32) -> P (invalid cols get exact 0).
#define QK_Q    0
#define QK_K0   ABYTES
#define QK_SMEM (3*ABYTES)          // 55296

__global__ void __launch_bounds__(256, 2)
qk_softmax(const __half* __restrict__ Q, const __half* __restrict__ Kg,
           __half* __restrict__ S, __half* __restrict__ P)
{
    extern __shared__ char dsm[];
    const int tid = threadIdx.x, w = tid >> 5, lane = tid & 31;
    const int wm = w & 1, wn = w >> 1;
    const int hb = blockIdx.y;
    const int L  = g_len[hb & (BATCH-1)];
    const int bm = blockIdx.x * 128;
    if (bm >= L) return;

    const __half* Qg = Q  + ((long long)hb*LSEQ + bm) * DKH;
    const __half* Kb = Kg + (long long)hb*LSEQ*DKH;
    __half* Sp = S + (long long)hb*LSEQ*LSEQ;
    __half* Pp = P + (long long)hb*LSEQ*LSEQ;

    const uint32_t smem0 = smem_u32(dsm);
    const int nbt = (L + 127) >> 7;

    {
        #pragma unroll
        for (int i = 0; i < 4; i++) {
            const int idx = tid + i*256;
            const int row = idx >> 3, chk = idx & 7;
            cp16(smem0 + QK_Q + row*(ASTRH*2) + chk*16,
                 Qg + (long long)row*DKH + chk*8);
        }
    }
    auto load_k = [&](int j) {
        const uint32_t sk = smem0 + QK_K0 + (j & 1)*ABYTES;
        const int kr = j << 7;
        #pragma unroll
        for (int i = 0; i < 4; i++) {
            const int idx = tid + i*256;
            const int row = idx >> 3, chk = idx & 7;
            cp16(sk + row*(ASTRH*2) + chk*16,
                 Kb + (long long)(kr + row)*DKH + chk*8);
        }
        asm volatile("cp.async.commit_group;" ::: "memory");
    };
    load_k(0);

    const int lrow_a  = lane & 15;
    const int lkoff_a = (lane >> 4) * 8;
    const int lrow_b  = (lane & 7) + ((lane >> 4) << 3);
    const int lkoff_b = (lane & 8) ? 8 : 0;

    for (int j = 0; j < nbt; j++) {
        asm volatile("cp.async.wait_group 0;" ::: "memory");
        __syncthreads();
        if (j + 1 < nbt) load_k(j + 1);

        float acc[4][4][4];
        #pragma unroll
        for (int i = 0; i < 4; i++)
            #pragma unroll
            for (int jj = 0; jj < 4; jj++)
                #pragma unroll
                for (int q = 0; q < 4; q++) acc[i][jj][q] = 0.f;

        const uint32_t Abase = smem0 + QK_Q;
        const uint32_t Bbase = smem0 + QK_K0 + (j & 1)*ABYTES;
        #pragma unroll
        for (int ks = 0; ks < 4; ks++) {
            uint32_t af[4][4];
            #pragma unroll
            for (int mt = 0; mt < 4; mt++) {
                const uint32_t addr = Abase +
                    ((wm*64 + mt*16 + lrow_a)*ASTRH + ks*16 + lkoff_a) * 2;
                ldsm4(af[mt][0], af[mt][1], af[mt][2], af[mt][3], addr);
            }
            uint32_t bf[4][2];
            #pragma unroll
            for (int np = 0; np < 2; np++) {
                const uint32_t addr = Bbase +
                    ((wn*32 + np*16 + lrow_b)*ASTRH + ks*16 + lkoff_b) * 2;
                ldsm4(bf[np*2][0], bf[np*2][1], bf[np*2+1][0], bf[np*2+1][1], addr);
            }
            #pragma unroll
            for (int mt = 0; mt < 4; mt++)
                #pragma unroll
                for (int nt = 0; nt < 4; nt++)
                    mma_f16(acc[mt][nt][0], acc[mt][nt][1], acc[mt][nt][2], acc[mt][nt][3],
                            af[mt][0], af[mt][1], af[mt][2], af[mt][3],
                            bf[nt][0], bf[nt][1]);
        }

        const int cn0 = (j << 7) + wn*32 + (lane & 3)*2;
        #pragma unroll
        for (int mt = 0; mt < 4; mt++) {
            #pragma unroll
            for (int half_ = 0; half_ < 2; half_++) {
                const int m = bm + wm*64 + mt*16 + (lane >> 2) + half_*8;
                #pragma unroll
                for (int nt = 0; nt < 4; nt++) {
                    *reinterpret_cast<__half2*>(&Sp[(long long)m*LSEQ + cn0 + nt*8]) =
                        __floats2half2_rn(acc[mt][nt][half_*2 + 0],
                                          acc[mt][nt][half_*2 + 1]);
                }
            }
        }
    }

    // ---- sentinel fill: S cols [L, 1024) of this strip <- -60000h -----------
    {
        const __half2 nh2 = __floats2half2_rn(-60000.f, -60000.f);
        const uint32_t np = *reinterpret_cast<const uint32_t*>(&nh2);
        const int Lp = (L + 7) & ~7;
        const int edge = Lp - L;                   // 0..7 scalar elements/row
        if (edge) {
            for (int e = tid; e < edge*128; e += 256) {
                const int r = e / edge, c = L + (e - r*edge);
                Sp[(long long)(bm + r)*LSEQ + c] = __float2half_rn(-60000.f);
            }
        }
        const int nv = (LSEQ - Lp) >> 3;           // uint4 chunks per row
        if (nv) {
            const uint4 negv = {np, np, np, np};
            for (int e = tid; e < nv*128; e += 256) {
                const int r = e / nv, c8 = e - r*nv;
                *reinterpret_cast<uint4*>(&Sp[(long long)(bm + r)*LSEQ + Lp + c8*8]) = negv;
            }
        }
    }

    __syncthreads();

    // -------- mask-free softmax: warp w handles rows w*16 .. w*16+15 ---------
    for (int i = 0; i < 16; i++) {
        const int m = bm + w*16 + i;
        if (m >= L) continue;
        const uint4* rp = reinterpret_cast<const uint4*>(Sp + (long long)m*LSEQ);
        uint4 v[4];
        #pragma unroll
        for (int it = 0; it < 4; it++) v[it] = rp[lane + it*32];

        // pass 1: max via __hmax2 (exact)
        __half2 hm = __floats2half2_rn(-60000.f, -60000.f);
        #pragma unroll
        for (int it = 0; it < 4; it++) {
            const uint32_t* pw = reinterpret_cast<const uint32_t*>(&v[it]);
            #pragma unroll
            for (int q = 0; q < 4; q++)
                hm = __hmax2(hm, *reinterpret_cast<const __half2*>(&pw[q]));
        }
        const float2 fm = __half22float2(hm);
        float mx = fmaxf(fm.x, fm.y);
        #pragma unroll
        for (int o = 16; o; o >>= 1) mx = fmaxf(mx, __shfl_xor_sync(~0u, mx, o));
        mx *= 0.125f;

        // pass 2: single exp pass; pack unnormalized e back into v
        float s = 0.f;
        #pragma unroll
        for (int it = 0; it < 4; it++) {
            uint32_t* pw = reinterpret_cast<uint32_t*>(&v[it]);
            #pragma unroll
            for (int q = 0; q < 4; q++) {
                const float2 f = __half22float2(
                    *reinterpret_cast<const __half2*>(&pw[q]));
                const float e0 = __expf(f.x*0.125f - mx);
                const float e1 = __expf(f.y*0.125f - mx);
                s += e0 + e1;
                const __half2 h = __floats2half2_rn(e0, e1);
                pw[q] = *reinterpret_cast<const uint32_t*>(&h);
            }
        }
        #pragma unroll
        for (int o = 16; o; o >>= 1) s += __shfl_xor_sync(~0u, s, o);
        const float inv = 1.f / s;

        // pass 3: normalize in fp32, store
        uint4* op = reinterpret_cast<uint4*>(Pp + (long long)m*LSEQ);
        #pragma unroll
        for (int it = 0; it < 4; it++) {
            const uint32_t* pw = reinterpret_cast<const uint32_t*>(&v[it]);
            uint4 o;
            uint32_t* ow = reinterpret_cast<uint32_t*>(&o);
            #pragma unroll
            for (int q = 0; q < 4; q++) {
                const float2 f = __half22float2(
                    *reinterpret_cast<const __half2*>(&pw[q]));
                const __half2 h = __floats2half2_rn(f.x*inv, f.y*inv);
                ow[q] = *reinterpret_cast<const uint32_t*>(&h);
            }
            op[lane + it*32] = o;
        }
    }
}

// ---------------- head-gate softmax + weighted combine (fp16 in/out) ---------
__global__ void gate_combine(const __half* __restrict__ G,
                             const __half* __restrict__ O,
                             __half* __restrict__ Y) {
    const int HS4 = MTOT*DVH/4;
    const int i = blockIdx.x * blockDim.x + threadIdx.x;
    if (i >= HS4) return;
    const int m = i >> 7;
    if ((m & (LSEQ-1)) >= g_len[m >> 10]) return;

    const uint2* G4 = reinterpret_cast<const uint2*>(G);
    const uint2* O4 = reinterpret_cast<const uint2*>(O);
    float g[NHEAD][4];
    float mx0 = -1e30f, mx1 = -1e30f, mx2 = -1e30f, mx3 = -1e30f;
    #pragma unroll
    for (int h = 0; h < NHEAD; h++) {
        const uint2 u = G4[(long long)h*HS4 + i];
        const float2 a = __half22float2(*reinterpret_cast<const __half2*>(&u.x));
        const float2 b = __half22float2(*reinterpret_cast<const __half2*>(&u.y));
        g[h][0] = a.x; g[h][1] = a.y; g[h][2] = b.x; g[h][3] = b.y;
        mx0 = fmaxf(mx0, a.x); mx1 = fmaxf(mx1, a.y);
        mx2 = fmaxf(mx2, b.x); mx3 = fmaxf(mx3, b.y);
    }
    float acc0=0, acc1=0, acc2=0, acc3=0, s0=0, s1=0, s2=0, s3=0;
    #pragma unroll
    for (int h = 0; h < NHEAD; h++) {
        const uint2 u = O4[(long long)h*HS4 + i];
        const float2 a = __half22float2(*reinterpret_cast<const __half2*>(&u.x));
        const float2 b = __half22float2(*reinterpret_cast<const __half2*>(&u.y));
        const float e0 = __expf(g[h][0] - mx0), e1 = __expf(g[h][1] - mx1);
        const float e2 = __expf(g[h][2] - mx2), e3 = __expf(g[h][3] - mx3);
        s0 += e0; s1 += e1; s2 += e2; s3 += e3;
        acc0 += e0*a.x; acc1 += e1*a.y; acc2 += e2*b.x; acc3 += e3*b.y;
    }
    uint2 o;
    *reinterpret_cast<__half2*>(&o.x) = __floats2half2_rn(acc0/s0, acc1/s1);
    *reinterpret_cast<__half2*>(&o.y) = __floats2half2_rn(acc2/s2, acc3/s3);
    reinterpret_cast<uint2*>(Y)[i] = o;
}

// ---------------- launch ------------------------------------------------------
extern "C" void kernel_launch(void* const* d_in, const int* in_sizes, int n_in,
                              void* d_out, int out_size) {
    const float*         enc  = (const float*)d_in[0];
    const unsigned char* npm  = (const unsigned char*)d_in[1];
    const float* w_q  = (const float*)d_in[3];
    const float* b_q  = (const float*)d_in[4];
    const float* w_k  = (const float*)d_in[5];
    const float* b_k  = (const float*)d_in[6];
    const float* w_v  = (const float*)d_in[7];
    const float* b_v  = (const float*)d_in[8];
    const float* w_g  = (const float*)d_in[9];
    const float* b_g  = (const float*)d_in[10];
    const float* w_fc = (const float*)d_in[11];
    const float* b_fc = (const float*)d_in[12];
    float* out = (float*)d_out;

    __half *pEnc,*pWq,*pWk,*pWv,*pWg,*pWfc,*pQ,*pK,*pVt,*pS,*pP,*pO,*pG,*pY;
    cudaGetSymbolAddress((void**)&pEnc, g_ench);
    cudaGetSymbolAddress((void**)&pWq,  g_Wqh);
    cudaGetSymbolAddress((void**)&pWk,  g_Wkh);
    cudaGetSymbolAddress((void**)&pWv,  g_Wvh);
    cudaGetSymbolAddress((void**)&pWg,  g_Wgh);
    cudaGetSymbolAddress((void**)&pWfc, g_Wfch);
    cudaGetSymbolAddress((void**)&pQ,   g_Q);
    cudaGetSymbolAddress((void**)&pK,   g_K);
    cudaGetSymbolAddress((void**)&pVt,  g_Vt);
    cudaGetSymbolAddress((void**)&pS,   g_S);
    cudaGetSymbolAddress((void**)&pP,   g_P);
    cudaGetSymbolAddress((void**)&pO,   g_O);
    cudaGetSymbolAddress((void**)&pG,   g_G);
    cudaGetSymbolAddress((void**)&pY,   g_Y);

    cudaFuncSetAttribute(gemm_mma<5,1>, cudaFuncAttributeMaxDynamicSharedMemorySize, SMEM_SZ);
    cudaFuncSetAttribute(gemm_mma<7,3>, cudaFuncAttributeMaxDynamicSharedMemorySize, SMEM_SZ);
    cudaFuncSetAttribute(gemm_mma<3,1>, cudaFuncAttributeMaxDynamicSharedMemorySize, SMEM_SZ);
    cudaFuncSetAttribute(gemm_mma<4,4>, cudaFuncAttributeMaxDynamicSharedMemorySize, SMEM_SZ);
    cudaFuncSetAttribute(qk_softmax,    cudaFuncAttributeMaxDynamicSharedMemorySize, QK_SMEM);

    const int M = MTOT;
    dim3 blk(256);

    convert_inputs<<<(N_ENC + 3*N_WQ + 2*N_WV) / 1024, 256>>>(enc, w_q, w_k, w_v, w_g, w_fc);
    prep_mask<<<1, 256>>>(npm);

    gemm_mma<5,1><<<dim3(40, M/128, 1), blk, SMEM_SZ>>>(
        pEnc,0, pWq,0, M, NHEAD*DKH, DMODEL, pQ,0, b_q,0, nullptr,
        pWk, b_k, pK, pWv, b_v, pVt);
    qk_softmax<<<dim3(LSEQ/128, NHEAD*BATCH), blk, QK_SMEM>>>(pQ, pK, pS, pP);
    gemm_mma<7,3><<<dim3(DVH/128, LSEQ/128, NHEAD*BATCH), blk, SMEM_SZ>>>(
        pP,(long long)LSEQ*LSEQ, pVt,(long long)DVH*LSEQ,
        LSEQ, DVH, LSEQ, pO,(long long)LSEQ*DVH, nullptr,0, nullptr,
        nullptr,nullptr,nullptr, nullptr,nullptr,nullptr);
    gemm_mma<3,1><<<dim3(DVH/128, M/128, NHEAD), blk, SMEM_SZ>>>(
        pO,(long long)M*DVH, pWg,(long long)DVH*DMODEL,
        M, DVH, DMODEL, pG,(long long)M*DVH, b_g, DVH, nullptr,
        nullptr,nullptr,nullptr, nullptr,nullptr,nullptr);
    gate_combine<<<(M*DVH/4 + 255)/256, 256>>>(pG, pO, pY);
    gemm_mma<4,4><<<dim3(DMODEL/128, M/128, 1), blk, SMEM_SZ>>>(
        pY,0, pWfc,0, M, DMODEL, DVH, out,0, b_fc,0, enc,
        nullptr,nullptr,nullptr, nullptr,nullptr,nullptr);
}